// round 1
// baseline (speedup 1.0000x reference)
#include <cuda_runtime.h>
#include <math.h>
#include <float.h>

#define N_ENT  40000
#define N_REL  500
#define E_DIR  200000
#define E_2HOP 50000
#define E_TOT  250000
#define D_IN   128
#define D_EMB  256
#define NH     4

// ---------------- device scratch (static: no allocations allowed) ----------------
__device__ float g_hr[N_ENT*D_EMB];     // per-node "row" projection, heads concat
__device__ float g_hc[N_ENT*D_EMB];     // per-node "col" projection
__device__ float g_ent[N_ENT*D_EMB];    // init_embed @ W_entities
__device__ float g_x[N_ENT*D_EMB];      // layer-1 output, reused as x_final
__device__ float g_prow[N_ENT*D_EMB];   // x @ out_W[0:256]
__device__ float g_pcol[N_ENT*D_EMB];   // x @ out_W[256:512]
__device__ float g_agg[N_ENT*D_EMB];    // layer-1 attention accumulator
__device__ float g_out2[N_ENT*D_EMB];   // layer-2 attention accumulator
__device__ float g_relp[N_REL*D_EMB];   // init_rel @ W_heads[:,256:384,:] (heads concat)
__device__ float g_rel2p[N_REL*D_EMB];  // r @ out_W[512:768]
__device__ float g_r[N_REL*D_EMB];      // r = init_rel @ gat_W  (output #2)
__device__ float g_Bt[3*D_IN*D_EMB];    // repacked W_heads: [part][k][h*64+d]
__device__ float g_sr[N_ENT*NH];
__device__ float g_sc[N_ENT*NH];
__device__ float g_srel[N_REL*NH];
__device__ float g_s2r[N_ENT];
__device__ float g_s2c[N_ENT];
__device__ float g_srel2[N_REL];
__device__ float g_lw1[E_TOT*NH];       // logits, then exp-weights (layer 1)
__device__ float g_lw2[E_TOT];          // logits, then exp-weights (layer 2)
__device__ float g_max1[N_ENT*NH];
__device__ float g_sum1[N_ENT*NH];
__device__ float g_max2[N_ENT];
__device__ float g_sum2[N_ENT];
__device__ int   g_row[E_TOT];
__device__ int   g_col[E_TOT];
__device__ float g_colsum[D_EMB];
__device__ float g_colsq[D_EMB];

// ---------------- helpers ----------------
__device__ __forceinline__ void atomicMaxF(float* addr, float v) {
    int* ai = (int*)addr;
    int old = *ai;
    while (__int_as_float(old) < v) {
        int assumed = old;
        old = atomicCAS(ai, assumed, __float_as_int(v));
        if (old == assumed) break;
    }
}

__device__ __forceinline__ void red_add_v4(float* addr, float4 v) {
    asm volatile("red.global.add.v4.f32 [%0], {%1,%2,%3,%4};"
                 :: "l"(addr), "f"(v.x), "f"(v.y), "f"(v.z), "f"(v.w) : "memory");
}

// ---------------- init: zero accumulators / set -inf maxima ----------------
__global__ void k_init() {
    int i = blockIdx.x * blockDim.x + threadIdx.x;
    int stride = gridDim.x * blockDim.x;
    for (int idx = i; idx < N_ENT*D_EMB; idx += stride) { g_agg[idx] = 0.f; g_out2[idx] = 0.f; }
    for (int idx = i; idx < N_ENT*NH;   idx += stride) { g_sum1[idx] = 0.f; g_max1[idx] = -FLT_MAX; }
    for (int idx = i; idx < N_ENT;      idx += stride) { g_sum2[idx] = 0.f; g_max2[idx] = -FLT_MAX; }
    if (i < D_EMB) { g_colsum[i] = 0.f; g_colsq[i] = 0.f; }
}

// ---------------- repack W_heads (4,384,64) into 3 row-major (128,256) B mats ----------------
__global__ void k_repack(const float* __restrict__ W_heads) {
    int idx = blockIdx.x * blockDim.x + threadIdx.x;
    if (idx >= 3*D_IN*D_EMB) return;
    int part = idx / (D_IN*D_EMB);
    int rem  = idx - part*D_IN*D_EMB;
    int k = rem >> 8;             // 0..127
    int c = rem & 255;            // h*64+d
    int h = c >> 6;
    int d = c & 63;
    g_Bt[idx] = W_heads[h*384*64 + (part*128 + k)*64 + d];
}

// ---------------- edge list build ----------------
__global__ void k_edges(const int* __restrict__ edge_index, const int* __restrict__ ind2) {
    int e = blockIdx.x * blockDim.x + threadIdx.x;
    if (e >= E_TOT) return;
    int r, c;
    if (e < E_DIR) { r = edge_index[E_DIR + e]; c = edge_index[e]; }
    else { int j = e - E_DIR; r = ind2[j*4 + 3]; c = ind2[j*4 + 0]; }
    g_row[e] = r; g_col[e] = c;
}

// ---------------- fp32 SGEMM: C(MxN) = A(MxK) @ B(KxN), row-major, N%128==0, K%8==0 ----------------
__global__ void sgemm128(const float* __restrict__ A, const float* __restrict__ B,
                         float* __restrict__ C, int M, int N, int K) {
    __shared__ float As[8][128];
    __shared__ float Bs[8][128];
    int tid = threadIdx.x;
    int m0 = blockIdx.y * 128, n0 = blockIdx.x * 128;
    int arow = tid >> 1;
    int acol = (tid & 1) << 2;
    int brow = tid >> 5;
    int bcol = (tid & 31) << 2;
    int tx = (tid & 15) << 3;
    int ty = (tid >> 4) << 3;
    float acc[8][8];
    #pragma unroll
    for (int i = 0; i < 8; i++)
        #pragma unroll
        for (int j = 0; j < 8; j++) acc[i][j] = 0.f;

    for (int k0 = 0; k0 < K; k0 += 8) {
        float4 av = make_float4(0.f, 0.f, 0.f, 0.f);
        if (m0 + arow < M) av = *(const float4*)(A + (size_t)(m0 + arow)*K + k0 + acol);
        As[acol+0][arow] = av.x; As[acol+1][arow] = av.y;
        As[acol+2][arow] = av.z; As[acol+3][arow] = av.w;
        *(float4*)(&Bs[brow][bcol]) = *(const float4*)(B + (size_t)(k0 + brow)*N + n0 + bcol);
        __syncthreads();
        #pragma unroll
        for (int k = 0; k < 8; k++) {
            float4 a0 = *(float4*)&As[k][ty];
            float4 a1 = *(float4*)&As[k][ty+4];
            float4 b0 = *(float4*)&Bs[k][tx];
            float4 b1 = *(float4*)&Bs[k][tx+4];
            float ar[8] = {a0.x,a0.y,a0.z,a0.w,a1.x,a1.y,a1.z,a1.w};
            float br[8] = {b0.x,b0.y,b0.z,b0.w,b1.x,b1.y,b1.z,b1.w};
            #pragma unroll
            for (int i = 0; i < 8; i++)
                #pragma unroll
                for (int j = 0; j < 8; j++)
                    acc[i][j] += ar[i]*br[j];
        }
        __syncthreads();
    }
    #pragma unroll
    for (int i = 0; i < 8; i++) {
        int row = m0 + ty + i;
        if (row < M) {
            *(float4*)(C + (size_t)row*N + n0 + tx)     = make_float4(acc[i][0],acc[i][1],acc[i][2],acc[i][3]);
            *(float4*)(C + (size_t)row*N + n0 + tx + 4) = make_float4(acc[i][4],acc[i][5],acc[i][6],acc[i][7]);
        }
    }
}

// ---------------- per-node / per-rel attention scalars, layer 1 ----------------
__global__ void k_scal1(const float* __restrict__ a_heads) {
    int idx = blockIdx.x * blockDim.x + threadIdx.x;
    if (idx >= N_ENT*NH) return;
    int v = idx >> 2, h = idx & 3;
    const float* a = a_heads + h*64;
    const float* pr = g_hr + v*D_EMB + h*64;
    const float* pc = g_hc + v*D_EMB + h*64;
    float s1 = 0.f, s2 = 0.f;
    #pragma unroll 8
    for (int d = 0; d < 64; d++) { float av = a[d]; s1 += pr[d]*av; s2 += pc[d]*av; }
    g_sr[idx] = s1; g_sc[idx] = s2;
}

__global__ void k_srel1(const float* __restrict__ a_heads) {
    int idx = blockIdx.x * blockDim.x + threadIdx.x;
    if (idx >= N_REL*NH) return;
    int v = idx >> 2, h = idx & 3;
    const float* a = a_heads + h*64;
    const float* p = g_relp + v*D_EMB + h*64;
    float s = 0.f;
    #pragma unroll 8
    for (int d = 0; d < 64; d++) s += p[d]*a[d];
    g_srel[idx] = s;
}

// ---------------- layer-1 edge passes ----------------
__global__ void k_logit1(const int* __restrict__ et, const int* __restrict__ ind2) {
    int e = blockIdx.x * blockDim.x + threadIdx.x;
    if (e >= E_TOT) return;
    int r = g_row[e], c = g_col[e];
    float se[NH];
    if (e < E_DIR) {
        int t = et[e];
        #pragma unroll
        for (int h = 0; h < NH; h++) se[h] = g_srel[t*NH + h];
    } else {
        int j = e - E_DIR;
        int t0 = ind2[j*4 + 1], t1 = ind2[j*4 + 2];
        #pragma unroll
        for (int h = 0; h < NH; h++) se[h] = g_srel[t0*NH + h] + g_srel[t1*NH + h];
    }
    #pragma unroll
    for (int h = 0; h < NH; h++) {
        float z = g_sr[r*NH + h] + g_sc[c*NH + h] + se[h];
        z = (z > 0.f) ? z : 0.2f*z;
        g_lw1[e*NH + h] = z;
        atomicMaxF(&g_max1[r*NH + h], z);
    }
}

__global__ void k_exp1() {
    int e = blockIdx.x * blockDim.x + threadIdx.x;
    if (e >= E_TOT) return;
    int r = g_row[e];
    #pragma unroll
    for (int h = 0; h < NH; h++) {
        float w = expf(g_lw1[e*NH + h] - g_max1[r*NH + h]);
        g_lw1[e*NH + h] = w;
        atomicAdd(&g_sum1[r*NH + h], w);
    }
}

__global__ void k_agg1(const int* __restrict__ et, const int* __restrict__ ind2) {
    int idx = blockIdx.x * blockDim.x + threadIdx.x;
    if (idx >= E_TOT*64) return;
    int e  = idx >> 6;
    int d4 = (idx & 63) << 2;
    int h  = d4 >> 6;
    int r = g_row[e], c = g_col[e];
    float alpha = g_lw1[e*NH + h] / (g_sum1[r*NH + h] + 1e-16f);
    float4 v = *(const float4*)(g_hr + r*D_EMB + d4);
    float4 w = *(const float4*)(g_hc + c*D_EMB + d4);
    float4 p;
    if (e < E_DIR) {
        int t = et[e];
        p = *(const float4*)(g_relp + t*D_EMB + d4);
    } else {
        int j = e - E_DIR;
        int t0 = ind2[j*4 + 1], t1 = ind2[j*4 + 2];
        float4 p0 = *(const float4*)(g_relp + t0*D_EMB + d4);
        float4 p1 = *(const float4*)(g_relp + t1*D_EMB + d4);
        p = make_float4(p0.x+p1.x, p0.y+p1.y, p0.z+p1.z, p0.w+p1.w);
    }
    float4 s = make_float4(alpha*(v.x+w.x+p.x), alpha*(v.y+w.y+p.y),
                           alpha*(v.z+w.z+p.z), alpha*(v.w+w.w+p.w));
    red_add_v4(g_agg + r*D_EMB + d4, s);
}

__global__ void k_fin1() {
    int idx = blockIdx.x * blockDim.x + threadIdx.x;
    if (idx >= N_ENT*D_EMB) return;
    float z = g_agg[idx];
    g_x[idx] = (z > 0.f) ? z : expm1f(z);
}

// ---------------- per-node / per-rel attention scalars, layer 2 ----------------
__global__ void k_scal2(const float* __restrict__ out_a) {
    int gt = blockIdx.x * blockDim.x + threadIdx.x;
    int w = gt >> 5, lane = gt & 31;
    if (w >= N_ENT) return;
    float s1 = 0.f, s2 = 0.f;
    for (int d = lane; d < D_EMB; d += 32) {
        float av = out_a[d];
        s1 += g_prow[w*D_EMB + d]*av;
        s2 += g_pcol[w*D_EMB + d]*av;
    }
    #pragma unroll
    for (int off = 16; off > 0; off >>= 1) {
        s1 += __shfl_xor_sync(0xffffffffu, s1, off);
        s2 += __shfl_xor_sync(0xffffffffu, s2, off);
    }
    if (lane == 0) { g_s2r[w] = s1; g_s2c[w] = s2; }
}

__global__ void k_srel2(const float* __restrict__ out_a) {
    int v = blockIdx.x * blockDim.x + threadIdx.x;
    if (v >= N_REL) return;
    float s = 0.f;
    for (int d = 0; d < D_EMB; d++) s += g_rel2p[v*D_EMB + d]*out_a[d];
    g_srel2[v] = s;
}

// ---------------- layer-2 edge passes ----------------
__global__ void k_logit2(const int* __restrict__ et, const int* __restrict__ ind2) {
    int e = blockIdx.x * blockDim.x + threadIdx.x;
    if (e >= E_TOT) return;
    int r = g_row[e], c = g_col[e];
    float se;
    if (e < E_DIR) se = g_srel2[et[e]];
    else { int j = e - E_DIR; se = g_srel2[ind2[j*4+1]] + g_srel2[ind2[j*4+2]]; }
    float z = g_s2r[r] + g_s2c[c] + se;
    z = (z > 0.f) ? z : 0.2f*z;
    g_lw2[e] = z;
    atomicMaxF(&g_max2[r], z);
}

__global__ void k_exp2() {
    int e = blockIdx.x * blockDim.x + threadIdx.x;
    if (e >= E_TOT) return;
    int r = g_row[e];
    float w = expf(g_lw2[e] - g_max2[r]);
    g_lw2[e] = w;
    atomicAdd(&g_sum2[r], w);
}

__global__ void k_agg2(const int* __restrict__ et, const int* __restrict__ ind2) {
    int idx = blockIdx.x * blockDim.x + threadIdx.x;
    if (idx >= E_TOT*64) return;
    int e  = idx >> 6;
    int d4 = (idx & 63) << 2;
    int r = g_row[e], c = g_col[e];
    float alpha = g_lw2[e] / (g_sum2[r] + 1e-16f);
    float4 v = *(const float4*)(g_prow + r*D_EMB + d4);
    float4 w = *(const float4*)(g_pcol + c*D_EMB + d4);
    float4 p;
    if (e < E_DIR) {
        int t = et[e];
        p = *(const float4*)(g_rel2p + t*D_EMB + d4);
    } else {
        int j = e - E_DIR;
        int t0 = ind2[j*4 + 1], t1 = ind2[j*4 + 2];
        float4 p0 = *(const float4*)(g_rel2p + t0*D_EMB + d4);
        float4 p1 = *(const float4*)(g_rel2p + t1*D_EMB + d4);
        p = make_float4(p0.x+p1.x, p0.y+p1.y, p0.z+p1.z, p0.w+p1.w);
    }
    float4 s = make_float4(alpha*(v.x+w.x+p.x), alpha*(v.y+w.y+p.y),
                           alpha*(v.z+w.z+p.z), alpha*(v.w+w.w+p.w));
    red_add_v4(g_out2 + r*D_EMB + d4, s);
}

// ---------------- x_final = elu(out2) + ent, column stats ----------------
__global__ void k_fin2() {
    int j = threadIdx.x;                    // 256 columns
    int v0 = blockIdx.x * 200;
    float s = 0.f, sq = 0.f;
    for (int v = v0; v < v0 + 200 && v < N_ENT; v++) {
        float z = g_out2[v*D_EMB + j];
        z = (z > 0.f) ? z : expm1f(z);
        z += g_ent[v*D_EMB + j];
        g_x[v*D_EMB + j] = z;
        s += z; sq += z*z;
    }
    atomicAdd(&g_colsum[j], s);
    atomicAdd(&g_colsq[j], sq);
}

// ---------------- batchnorm + outputs ----------------
__global__ void k_bn_out(const float* __restrict__ gamma, const float* __restrict__ beta,
                         float* __restrict__ out) {
    int i = blockIdx.x * blockDim.x + threadIdx.x;
    if (i < N_ENT*D_EMB) {
        int j = i & 255;
        float mu  = g_colsum[j] * (1.f/N_ENT);
        float var = g_colsq[j] * (1.f/N_ENT) - mu*mu;
        out[i] = (g_x[i] - mu) * rsqrtf(var + 1e-5f) * gamma[j] + beta[j];
    } else if (i < N_ENT*D_EMB + N_REL*D_EMB) {
        out[i] = g_r[i - N_ENT*D_EMB];
    }
}

// ---------------- launch ----------------
extern "C" void kernel_launch(void* const* d_in, const int* in_sizes, int n_in,
                              void* d_out, int out_size) {
    const int*   edge_index = (const int*)d_in[0];
    const int*   edge_type  = (const int*)d_in[1];
    const int*   ind2       = (const int*)d_in[2];
    const float* init_embed = (const float*)d_in[3];
    const float* init_rel   = (const float*)d_in[4];
    const float* W_heads    = (const float*)d_in[5];
    const float* a_heads    = (const float*)d_in[6];
    const float* gat_W      = (const float*)d_in[7];
    const float* out_W      = (const float*)d_in[8];
    const float* out_a      = (const float*)d_in[9];
    const float* W_entities = (const float*)d_in[10];
    const float* bn_gamma   = (const float*)d_in[11];
    const float* bn_beta    = (const float*)d_in[12];
    float* out = (float*)d_out;

    float *p_hr, *p_hc, *p_ent, *p_x, *p_prow, *p_pcol, *p_relp, *p_rel2p, *p_r, *p_Bt;
    cudaGetSymbolAddress((void**)&p_hr,    g_hr);
    cudaGetSymbolAddress((void**)&p_hc,    g_hc);
    cudaGetSymbolAddress((void**)&p_ent,   g_ent);
    cudaGetSymbolAddress((void**)&p_x,     g_x);
    cudaGetSymbolAddress((void**)&p_prow,  g_prow);
    cudaGetSymbolAddress((void**)&p_pcol,  g_pcol);
    cudaGetSymbolAddress((void**)&p_relp,  g_relp);
    cudaGetSymbolAddress((void**)&p_rel2p, g_rel2p);
    cudaGetSymbolAddress((void**)&p_r,     g_r);
    cudaGetSymbolAddress((void**)&p_Bt,    g_Bt);

    const int TB = 256;
    // init + prep
    k_init<<<(N_ENT*D_EMB + TB-1)/TB, TB>>>();
    k_repack<<<(3*D_IN*D_EMB + TB-1)/TB, TB>>>(W_heads);
    k_edges<<<(E_TOT + TB-1)/TB, TB>>>(edge_index, ind2);

    // layer-1 GEMMs (+ ent, r)
    dim3 gN(D_EMB/128, (N_ENT + 127)/128);
    dim3 gR(D_EMB/128, (N_REL + 127)/128);
    sgemm128<<<gN, TB>>>(init_embed, p_Bt,               p_hr,   N_ENT, D_EMB, D_IN);
    sgemm128<<<gN, TB>>>(init_embed, p_Bt + D_IN*D_EMB,  p_hc,   N_ENT, D_EMB, D_IN);
    sgemm128<<<gR, TB>>>(init_rel,   p_Bt + 2*D_IN*D_EMB,p_relp, N_REL, D_EMB, D_IN);
    sgemm128<<<gN, TB>>>(init_embed, W_entities,         p_ent,  N_ENT, D_EMB, D_IN);
    sgemm128<<<gR, TB>>>(init_rel,   gat_W,              p_r,    N_REL, D_EMB, D_IN);

    // layer-1 attention
    k_scal1<<<(N_ENT*NH + TB-1)/TB, TB>>>(a_heads);
    k_srel1<<<(N_REL*NH + TB-1)/TB, TB>>>(a_heads);
    k_logit1<<<(E_TOT + TB-1)/TB, TB>>>(edge_type, ind2);
    k_exp1<<<(E_TOT + TB-1)/TB, TB>>>();
    k_agg1<<<(E_TOT*64 + TB-1)/TB, TB>>>(edge_type, ind2);
    k_fin1<<<(N_ENT*D_EMB + TB-1)/TB, TB>>>();

    // layer-2 GEMMs
    sgemm128<<<gN, TB>>>(p_x, out_W,               p_prow,  N_ENT, D_EMB, D_EMB);
    sgemm128<<<gN, TB>>>(p_x, out_W + 256*D_EMB,   p_pcol,  N_ENT, D_EMB, D_EMB);
    sgemm128<<<gR, TB>>>(p_r, out_W + 512*D_EMB,   p_rel2p, N_REL, D_EMB, D_EMB);

    // layer-2 attention
    k_scal2<<<(N_ENT*32 + TB-1)/TB, TB>>>(out_a);
    k_srel2<<<(N_REL + TB-1)/TB, TB>>>(out_a);
    k_logit2<<<(E_TOT + TB-1)/TB, TB>>>(edge_type, ind2);
    k_exp2<<<(E_TOT + TB-1)/TB, TB>>>();
    k_agg2<<<(E_TOT*64 + TB-1)/TB, TB>>>(edge_type, ind2);

    // finalize + BN + write outputs
    k_fin2<<<200, 256>>>();
    k_bn_out<<<(N_ENT*D_EMB + N_REL*D_EMB + TB-1)/TB, TB>>>(bn_gamma, bn_beta, out);
}

// round 2
// speedup vs baseline: 1.1830x; 1.1830x over previous
#include <cuda_runtime.h>
#include <math.h>
#include <float.h>
#include <stdint.h>

#define N_ENT  40000
#define N_REL  500
#define E_DIR  200000
#define E_2HOP 50000
#define E_TOT  250000
#define D_IN   128
#define D_EMB  256
#define NH     4

// ---------------- device scratch ----------------
__device__ float g_big1[N_ENT*768];     // [hr | hc | ent], row stride 768
__device__ float g_big2[N_ENT*512];     // [prow | pcol], row stride 512
__device__ float g_relcat[N_REL*512];   // [relp | r], row stride 512
__device__ float g_rel2p[N_REL*D_EMB];  // r @ out_W[512:768]
__device__ float g_x[N_ENT*D_EMB];      // layer-1 output / x_final
__device__ float g_agg[N_ENT*D_EMB];
__device__ float g_out2[N_ENT*D_EMB];
__device__ float g_B1[128*768];         // [Wh_part0 | Wh_part1 | W_entities]
__device__ float g_B1r[128*512];        // [Wh_part2 | gat_W]
__device__ float g_B2[256*512];         // [out_W rows 0:256 | rows 256:512]
__device__ float g_B2r[256*256];        // out_W rows 512:768 (contiguous copy)
__device__ float g_sr[N_ENT*NH];
__device__ float g_sc[N_ENT*NH];
__device__ float g_srel[N_REL*NH];
__device__ float g_s2r[N_ENT];
__device__ float g_s2c[N_ENT];
__device__ float g_srel2[N_REL];
__device__ float g_lw1[E_TOT*NH];
__device__ float g_lw2[E_TOT];
__device__ float g_max1[N_ENT*NH];
__device__ float g_sum1[N_ENT*NH];
__device__ float g_max2[N_ENT];
__device__ float g_sum2[N_ENT];
__device__ int   g_row[E_TOT];
__device__ int   g_col[E_TOT];
__device__ float g_colsum[D_EMB];
__device__ float g_colsq[D_EMB];

// ---------------- helpers ----------------
__device__ __forceinline__ void atomicMaxF(float* addr, float v) {
    int* ai = (int*)addr;
    int old = *ai;
    while (__int_as_float(old) < v) {
        int assumed = old;
        old = atomicCAS(ai, assumed, __float_as_int(v));
        if (old == assumed) break;
    }
}

__device__ __forceinline__ void red_add_v4(float* addr, float4 v) {
    asm volatile("red.global.add.v4.f32 [%0], {%1,%2,%3,%4};"
                 :: "l"(addr), "f"(v.x), "f"(v.y), "f"(v.z), "f"(v.w) : "memory");
}

__device__ __forceinline__ uint32_t f2tf(float x) {
    uint32_t u;
    asm("cvt.rna.tf32.f32 %0, %1;" : "=r"(u) : "f"(x));
    return u;
}

__device__ __forceinline__ void mma8(float* c, const uint32_t* a, const uint32_t* b) {
    asm volatile(
        "mma.sync.aligned.m16n8k8.row.col.f32.tf32.tf32.f32 "
        "{%0,%1,%2,%3},{%4,%5,%6,%7},{%8,%9},{%0,%1,%2,%3};"
        : "+f"(c[0]), "+f"(c[1]), "+f"(c[2]), "+f"(c[3])
        : "r"(a[0]), "r"(a[1]), "r"(a[2]), "r"(a[3]), "r"(b[0]), "r"(b[1]));
}

// ---------------- init ----------------
__global__ void k_init() {
    int i = blockIdx.x * blockDim.x + threadIdx.x;
    int stride = gridDim.x * blockDim.x;
    for (int idx = i; idx < N_ENT*D_EMB; idx += stride) { g_agg[idx] = 0.f; g_out2[idx] = 0.f; }
    for (int idx = i; idx < N_ENT*NH;   idx += stride) { g_sum1[idx] = 0.f; g_max1[idx] = -FLT_MAX; }
    for (int idx = i; idx < N_ENT;      idx += stride) { g_sum2[idx] = 0.f; g_max2[idx] = -FLT_MAX; }
    if (i < D_EMB) { g_colsum[i] = 0.f; g_colsq[i] = 0.f; }
}

// ---------------- weight repacks ----------------
__global__ void k_repackB1(const float* __restrict__ W_heads, const float* __restrict__ W_entities) {
    int idx = blockIdx.x * blockDim.x + threadIdx.x;
    if (idx >= 128*768) return;
    int k = idx / 768, c = idx % 768;
    float v;
    if (c < 512) {
        int part = c >> 8;
        int cc = c & 255;
        int h = cc >> 6, d = cc & 63;
        v = W_heads[h*384*64 + (part*128 + k)*64 + d];
    } else {
        v = W_entities[k*256 + (c - 512)];
    }
    g_B1[idx] = v;
}

__global__ void k_repackB1r(const float* __restrict__ W_heads, const float* __restrict__ gat_W) {
    int idx = blockIdx.x * blockDim.x + threadIdx.x;
    if (idx >= 128*512) return;
    int k = idx / 512, c = idx % 512;
    float v;
    if (c < 256) {
        int h = c >> 6, d = c & 63;
        v = W_heads[h*384*64 + (256 + k)*64 + d];
    } else {
        v = gat_W[k*256 + (c - 256)];
    }
    g_B1r[idx] = v;
}

__global__ void k_repackB2(const float* __restrict__ out_W) {
    int idx = blockIdx.x * blockDim.x + threadIdx.x;
    if (idx < 256*512) {
        int k = idx / 512, c = idx % 512;
        g_B2[idx] = (c < 256) ? out_W[k*256 + c] : out_W[(256 + k)*256 + (c - 256)];
    }
    if (idx < 256*256) {
        g_B2r[idx] = out_W[512*256 + idx];
    }
}

// ---------------- edge list build ----------------
__global__ void k_edges(const int* __restrict__ edge_index, const int* __restrict__ ind2) {
    int e = blockIdx.x * blockDim.x + threadIdx.x;
    if (e >= E_TOT) return;
    int r, c;
    if (e < E_DIR) { r = edge_index[E_DIR + e]; c = edge_index[e]; }
    else { int j = e - E_DIR; r = ind2[j*4 + 3]; c = ind2[j*4 + 0]; }
    g_row[e] = r; g_col[e] = c;
}

// ---------------- 3xTF32 tensor-core GEMM ----------------
__global__ __launch_bounds__(256, 1) void gemm_tf32(
    const float* __restrict__ A, const float* __restrict__ B, float* __restrict__ C,
    int M, int N, int K, int lda, int ldc)
{
    __shared__ float As[128][36];
    __shared__ float Bs[32][136];

    int tid  = threadIdx.x;
    int m0   = blockIdx.y * 128;
    int n0   = blockIdx.x * 128;
    int warp = tid >> 5;
    int lane = tid & 31;
    int g = lane >> 2;
    int t = lane & 3;
    int wm = warp >> 1;
    int wn = warp & 1;

    float acc[2][8][4];
    #pragma unroll
    for (int i = 0; i < 2; i++)
        #pragma unroll
        for (int j = 0; j < 8; j++)
            #pragma unroll
            for (int q = 0; q < 4; q++) acc[i][j][q] = 0.f;

    for (int k0 = 0; k0 < K; k0 += 32) {
        #pragma unroll
        for (int i = 0; i < 4; i++) {
            int s = tid + i*256;
            int row = s >> 3;
            int k4  = (s & 7) << 2;
            float4 v = make_float4(0.f, 0.f, 0.f, 0.f);
            if (m0 + row < M)
                v = *(const float4*)(A + (size_t)(m0 + row)*lda + k0 + k4);
            *(float4*)(&As[row][k4]) = v;
        }
        #pragma unroll
        for (int i = 0; i < 4; i++) {
            int s = tid + i*256;
            int k  = s >> 5;
            int n4 = (s & 31) << 2;
            *(float4*)(&Bs[k][n4]) = *(const float4*)(B + (size_t)(k0 + k)*N + n0 + n4);
        }
        __syncthreads();

        #pragma unroll
        for (int ks = 0; ks < 4; ks++) {
            int kk = ks * 8;
            uint32_t ahi[2][4], alo[2][4];
            #pragma unroll
            for (int i = 0; i < 2; i++) {
                int rb = wm*32 + i*16;
                float r0 = As[rb + g][kk + t];
                float r1 = As[rb + g + 8][kk + t];
                float r2 = As[rb + g][kk + t + 4];
                float r3 = As[rb + g + 8][kk + t + 4];
                ahi[i][0] = f2tf(r0); alo[i][0] = f2tf(r0 - __uint_as_float(ahi[i][0]));
                ahi[i][1] = f2tf(r1); alo[i][1] = f2tf(r1 - __uint_as_float(ahi[i][1]));
                ahi[i][2] = f2tf(r2); alo[i][2] = f2tf(r2 - __uint_as_float(ahi[i][2]));
                ahi[i][3] = f2tf(r3); alo[i][3] = f2tf(r3 - __uint_as_float(ahi[i][3]));
            }
            uint32_t bhi[8][2], blo[8][2];
            #pragma unroll
            for (int j = 0; j < 8; j++) {
                int nb = wn*64 + j*8 + g;
                float r0 = Bs[kk + t][nb];
                float r1 = Bs[kk + t + 4][nb];
                bhi[j][0] = f2tf(r0); blo[j][0] = f2tf(r0 - __uint_as_float(bhi[j][0]));
                bhi[j][1] = f2tf(r1); blo[j][1] = f2tf(r1 - __uint_as_float(bhi[j][1]));
            }
            #pragma unroll
            for (int i = 0; i < 2; i++)
                #pragma unroll
                for (int j = 0; j < 8; j++) {
                    mma8(acc[i][j], ahi[i], bhi[j]);
                    mma8(acc[i][j], ahi[i], blo[j]);
                    mma8(acc[i][j], alo[i], bhi[j]);
                }
        }
        __syncthreads();
    }

    #pragma unroll
    for (int i = 0; i < 2; i++) {
        int r0 = m0 + wm*32 + i*16 + g;
        #pragma unroll
        for (int j = 0; j < 8; j++) {
            int col = n0 + wn*64 + j*8 + 2*t;
            if (r0 < M)
                *(float2*)(C + (size_t)r0*ldc + col) = make_float2(acc[i][j][0], acc[i][j][1]);
            if (r0 + 8 < M)
                *(float2*)(C + (size_t)(r0 + 8)*ldc + col) = make_float2(acc[i][j][2], acc[i][j][3]);
        }
    }
}

// ---------------- per-node / per-rel attention scalars, layer 1 ----------------
__global__ void k_scal1(const float* __restrict__ a_heads) {
    int idx = blockIdx.x * blockDim.x + threadIdx.x;
    if (idx >= N_ENT*NH) return;
    int v = idx >> 2, h = idx & 3;
    const float* a = a_heads + h*64;
    const float* pr = g_big1 + (size_t)v*768 + h*64;
    const float* pc = g_big1 + (size_t)v*768 + 256 + h*64;
    float s1 = 0.f, s2 = 0.f;
    #pragma unroll 8
    for (int d = 0; d < 64; d++) { float av = a[d]; s1 += pr[d]*av; s2 += pc[d]*av; }
    g_sr[idx] = s1; g_sc[idx] = s2;
}

__global__ void k_srel1(const float* __restrict__ a_heads) {
    int idx = blockIdx.x * blockDim.x + threadIdx.x;
    if (idx >= N_REL*NH) return;
    int v = idx >> 2, h = idx & 3;
    const float* a = a_heads + h*64;
    const float* p = g_relcat + v*512 + h*64;
    float s = 0.f;
    #pragma unroll 8
    for (int d = 0; d < 64; d++) s += p[d]*a[d];
    g_srel[idx] = s;
}

// ---------------- layer-1 edge passes ----------------
__global__ void k_logit1(const int* __restrict__ et, const int* __restrict__ ind2) {
    int e = blockIdx.x * blockDim.x + threadIdx.x;
    if (e >= E_TOT) return;
    int r = g_row[e], c = g_col[e];
    float se[NH];
    if (e < E_DIR) {
        int tt = et[e];
        #pragma unroll
        for (int h = 0; h < NH; h++) se[h] = g_srel[tt*NH + h];
    } else {
        int j = e - E_DIR;
        int t0 = ind2[j*4 + 1], t1 = ind2[j*4 + 2];
        #pragma unroll
        for (int h = 0; h < NH; h++) se[h] = g_srel[t0*NH + h] + g_srel[t1*NH + h];
    }
    #pragma unroll
    for (int h = 0; h < NH; h++) {
        float z = g_sr[r*NH + h] + g_sc[c*NH + h] + se[h];
        z = (z > 0.f) ? z : 0.2f*z;
        g_lw1[e*NH + h] = z;
        atomicMaxF(&g_max1[r*NH + h], z);
    }
}

__global__ void k_exp1() {
    int e = blockIdx.x * blockDim.x + threadIdx.x;
    if (e >= E_TOT) return;
    int r = g_row[e];
    #pragma unroll
    for (int h = 0; h < NH; h++) {
        float w = expf(g_lw1[e*NH + h] - g_max1[r*NH + h]);
        g_lw1[e*NH + h] = w;
        atomicAdd(&g_sum1[r*NH + h], w);
    }
}

__global__ void k_agg1(const int* __restrict__ et, const int* __restrict__ ind2) {
    int idx = blockIdx.x * blockDim.x + threadIdx.x;
    if (idx >= E_TOT*64) return;
    int e  = idx >> 6;
    int d4 = (idx & 63) << 2;
    int h  = d4 >> 6;
    int r = g_row[e], c = g_col[e];
    float alpha = g_lw1[e*NH + h] / (g_sum1[r*NH + h] + 1e-16f);
    float4 v = *(const float4*)(g_big1 + (size_t)r*768 + d4);
    float4 w = *(const float4*)(g_big1 + (size_t)c*768 + 256 + d4);
    float4 p;
    if (e < E_DIR) {
        int tt = et[e];
        p = *(const float4*)(g_relcat + tt*512 + d4);
    } else {
        int j = e - E_DIR;
        int t0 = ind2[j*4 + 1], t1 = ind2[j*4 + 2];
        float4 p0 = *(const float4*)(g_relcat + t0*512 + d4);
        float4 p1 = *(const float4*)(g_relcat + t1*512 + d4);
        p = make_float4(p0.x+p1.x, p0.y+p1.y, p0.z+p1.z, p0.w+p1.w);
    }
    float4 s = make_float4(alpha*(v.x+w.x+p.x), alpha*(v.y+w.y+p.y),
                           alpha*(v.z+w.z+p.z), alpha*(v.w+w.w+p.w));
    red_add_v4(g_agg + (size_t)r*D_EMB + d4, s);
}

__global__ void k_fin1() {
    int idx = blockIdx.x * blockDim.x + threadIdx.x;
    if (idx >= N_ENT*D_EMB) return;
    float z = g_agg[idx];
    g_x[idx] = (z > 0.f) ? z : expm1f(z);
}

// ---------------- layer-2 scalars ----------------
__global__ void k_scal2(const float* __restrict__ out_a) {
    int gt = blockIdx.x * blockDim.x + threadIdx.x;
    int w = gt >> 5, lane = gt & 31;
    if (w >= N_ENT) return;
    float s1 = 0.f, s2 = 0.f;
    for (int d = lane; d < D_EMB; d += 32) {
        float av = out_a[d];
        s1 += g_big2[(size_t)w*512 + d]*av;
        s2 += g_big2[(size_t)w*512 + 256 + d]*av;
    }
    #pragma unroll
    for (int off = 16; off > 0; off >>= 1) {
        s1 += __shfl_xor_sync(0xffffffffu, s1, off);
        s2 += __shfl_xor_sync(0xffffffffu, s2, off);
    }
    if (lane == 0) { g_s2r[w] = s1; g_s2c[w] = s2; }
}

__global__ void k_srel2(const float* __restrict__ out_a) {
    int v = blockIdx.x * blockDim.x + threadIdx.x;
    if (v >= N_REL) return;
    float s = 0.f;
    for (int d = 0; d < D_EMB; d++) s += g_rel2p[v*D_EMB + d]*out_a[d];
    g_srel2[v] = s;
}

// ---------------- layer-2 edge passes ----------------
__global__ void k_logit2(const int* __restrict__ et, const int* __restrict__ ind2) {
    int e = blockIdx.x * blockDim.x + threadIdx.x;
    if (e >= E_TOT) return;
    int r = g_row[e], c = g_col[e];
    float se;
    if (e < E_DIR) se = g_srel2[et[e]];
    else { int j = e - E_DIR; se = g_srel2[ind2[j*4+1]] + g_srel2[ind2[j*4+2]]; }
    float z = g_s2r[r] + g_s2c[c] + se;
    z = (z > 0.f) ? z : 0.2f*z;
    g_lw2[e] = z;
    atomicMaxF(&g_max2[r], z);
}

__global__ void k_exp2() {
    int e = blockIdx.x * blockDim.x + threadIdx.x;
    if (e >= E_TOT) return;
    int r = g_row[e];
    float w = expf(g_lw2[e] - g_max2[r]);
    g_lw2[e] = w;
    atomicAdd(&g_sum2[r], w);
}

__global__ void k_agg2(const int* __restrict__ et, const int* __restrict__ ind2) {
    int idx = blockIdx.x * blockDim.x + threadIdx.x;
    if (idx >= E_TOT*64) return;
    int e  = idx >> 6;
    int d4 = (idx & 63) << 2;
    int r = g_row[e], c = g_col[e];
    float alpha = g_lw2[e] / (g_sum2[r] + 1e-16f);
    float4 v = *(const float4*)(g_big2 + (size_t)r*512 + d4);
    float4 w = *(const float4*)(g_big2 + (size_t)c*512 + 256 + d4);
    float4 p;
    if (e < E_DIR) {
        int tt = et[e];
        p = *(const float4*)(g_rel2p + tt*D_EMB + d4);
    } else {
        int j = e - E_DIR;
        int t0 = ind2[j*4 + 1], t1 = ind2[j*4 + 2];
        float4 p0 = *(const float4*)(g_rel2p + t0*D_EMB + d4);
        float4 p1 = *(const float4*)(g_rel2p + t1*D_EMB + d4);
        p = make_float4(p0.x+p1.x, p0.y+p1.y, p0.z+p1.z, p0.w+p1.w);
    }
    float4 s = make_float4(alpha*(v.x+w.x+p.x), alpha*(v.y+w.y+p.y),
                           alpha*(v.z+w.z+p.z), alpha*(v.w+w.w+p.w));
    red_add_v4(g_out2 + (size_t)r*D_EMB + d4, s);
}

// ---------------- finalize + BN ----------------
__global__ void k_fin2() {
    int j = threadIdx.x;
    int v0 = blockIdx.x * 200;
    float s = 0.f, sq = 0.f;
    for (int v = v0; v < v0 + 200 && v < N_ENT; v++) {
        float z = g_out2[(size_t)v*D_EMB + j];
        z = (z > 0.f) ? z : expm1f(z);
        z += g_big1[(size_t)v*768 + 512 + j];
        g_x[(size_t)v*D_EMB + j] = z;
        s += z; sq += z*z;
    }
    atomicAdd(&g_colsum[j], s);
    atomicAdd(&g_colsq[j], sq);
}

__global__ void k_bn_out(const float* __restrict__ gamma, const float* __restrict__ beta,
                         float* __restrict__ out) {
    int i = blockIdx.x * blockDim.x + threadIdx.x;
    if (i < N_ENT*D_EMB) {
        int j = i & 255;
        float mu  = g_colsum[j] * (1.f/N_ENT);
        float var = g_colsq[j] * (1.f/N_ENT) - mu*mu;
        out[i] = (g_x[i] - mu) * rsqrtf(var + 1e-5f) * gamma[j] + beta[j];
    } else if (i < N_ENT*D_EMB + N_REL*D_EMB) {
        int j = i - N_ENT*D_EMB;
        int v = j >> 8, c = j & 255;
        out[i] = g_relcat[v*512 + 256 + c];
    }
}

// ---------------- launch ----------------
extern "C" void kernel_launch(void* const* d_in, const int* in_sizes, int n_in,
                              void* d_out, int out_size) {
    const int*   edge_index = (const int*)d_in[0];
    const int*   edge_type  = (const int*)d_in[1];
    const int*   ind2       = (const int*)d_in[2];
    const float* init_embed = (const float*)d_in[3];
    const float* init_rel   = (const float*)d_in[4];
    const float* W_heads    = (const float*)d_in[5];
    const float* a_heads    = (const float*)d_in[6];
    const float* gat_W      = (const float*)d_in[7];
    const float* out_W      = (const float*)d_in[8];
    const float* out_a      = (const float*)d_in[9];
    const float* W_entities = (const float*)d_in[10];
    const float* bn_gamma   = (const float*)d_in[11];
    const float* bn_beta    = (const float*)d_in[12];
    float* out = (float*)d_out;

    float *p_big1, *p_big2, *p_relcat, *p_rel2p, *p_x, *p_B1, *p_B1r, *p_B2, *p_B2r;
    cudaGetSymbolAddress((void**)&p_big1,   g_big1);
    cudaGetSymbolAddress((void**)&p_big2,   g_big2);
    cudaGetSymbolAddress((void**)&p_relcat, g_relcat);
    cudaGetSymbolAddress((void**)&p_rel2p,  g_rel2p);
    cudaGetSymbolAddress((void**)&p_x,      g_x);
    cudaGetSymbolAddress((void**)&p_B1,     g_B1);
    cudaGetSymbolAddress((void**)&p_B1r,    g_B1r);
    cudaGetSymbolAddress((void**)&p_B2,     g_B2);
    cudaGetSymbolAddress((void**)&p_B2r,    g_B2r);

    const int TB = 256;
    k_init<<<(N_ENT*D_EMB + TB-1)/TB, TB>>>();
    k_repackB1<<<(128*768 + TB-1)/TB, TB>>>(W_heads, W_entities);
    k_repackB1r<<<(128*512 + TB-1)/TB, TB>>>(W_heads, gat_W);
    k_repackB2<<<(256*512 + TB-1)/TB, TB>>>(out_W);
    k_edges<<<(E_TOT + TB-1)/TB, TB>>>(edge_index, ind2);

    // layer-1 GEMMs
    gemm_tf32<<<dim3(768/128, (N_ENT + 127)/128), 256>>>(init_embed, p_B1, p_big1,
                                                          N_ENT, 768, 128, 128, 768);
    gemm_tf32<<<dim3(512/128, (N_REL + 127)/128), 256>>>(init_rel, p_B1r, p_relcat,
                                                          N_REL, 512, 128, 128, 512);

    // layer-1 attention
    k_scal1<<<(N_ENT*NH + TB-1)/TB, TB>>>(a_heads);
    k_srel1<<<(N_REL*NH + TB-1)/TB, TB>>>(a_heads);
    k_logit1<<<(E_TOT + TB-1)/TB, TB>>>(edge_type, ind2);
    k_exp1<<<(E_TOT + TB-1)/TB, TB>>>();
    k_agg1<<<(E_TOT*64 + TB-1)/TB, TB>>>(edge_type, ind2);
    k_fin1<<<(N_ENT*D_EMB + TB-1)/TB, TB>>>();

    // layer-2 GEMMs
    gemm_tf32<<<dim3(512/128, (N_ENT + 127)/128), 256>>>(p_x, p_B2, p_big2,
                                                          N_ENT, 512, 256, 256, 512);
    gemm_tf32<<<dim3(256/128, (N_REL + 127)/128), 256>>>(p_relcat + 256, p_B2r, p_rel2p,
                                                          N_REL, 256, 256, 512, 256);

    // layer-2 attention
    k_scal2<<<(N_ENT*32 + TB-1)/TB, TB>>>(out_a);
    k_srel2<<<(N_REL + TB-1)/TB, TB>>>(out_a);
    k_logit2<<<(E_TOT + TB-1)/TB, TB>>>(edge_type, ind2);
    k_exp2<<<(E_TOT + TB-1)/TB, TB>>>();
    k_agg2<<<(E_TOT*64 + TB-1)/TB, TB>>>(edge_type, ind2);

    k_fin2<<<200, 256>>>();
    k_bn_out<<<(N_ENT*D_EMB + N_REL*D_EMB + TB-1)/TB, TB>>>(bn_gamma, bn_beta, out);
}

// round 3
// speedup vs baseline: 1.2248x; 1.0354x over previous
#include <cuda_runtime.h>
#include <math.h>
#include <float.h>
#include <stdint.h>

#define N_ENT  40000
#define N_REL  500
#define E_DIR  200000
#define E_2HOP 50000
#define E_TOT  250000
#define D_IN   128
#define D_EMB  256
#define NH     4

// ---------------- device scratch (compact, stride-256 buffers) ----------------
__device__ float g_hr[N_ENT*D_EMB];
__device__ float g_hc[N_ENT*D_EMB];
__device__ float g_ent[N_ENT*D_EMB];
__device__ float g_prow[N_ENT*D_EMB];
__device__ float g_pcol[N_ENT*D_EMB];
__device__ float g_relp[N_REL*D_EMB];
__device__ float g_r[N_REL*D_EMB];
__device__ float g_rel2p[N_REL*D_EMB];
__device__ float g_x[N_ENT*D_EMB];
__device__ float g_agg[N_ENT*D_EMB];
__device__ float g_out2[N_ENT*D_EMB];
__device__ float g_B1[128*768];         // [Wh_part0 | Wh_part1 | W_entities]
__device__ float g_B1r[128*512];        // [Wh_part2 | gat_W]
__device__ float g_B2[256*512];         // [out_W rows 0:256 | rows 256:512]
__device__ float g_B2r[256*256];        // out_W rows 512:768
__device__ float g_sr[N_ENT*NH];
__device__ float g_sc[N_ENT*NH];
__device__ float g_srel[N_REL*NH];
__device__ float g_s2r[N_ENT];
__device__ float g_s2c[N_ENT];
__device__ float g_srel2[N_REL];
__device__ float g_lw1[E_TOT*NH];
__device__ float g_lw2[E_TOT];
__device__ float g_sum1[N_ENT*NH];
__device__ float g_sum2[N_ENT];
__device__ int   g_row[E_TOT];
__device__ int   g_col[E_TOT];
__device__ float g_colsum[D_EMB];
__device__ float g_colsq[D_EMB];

// ---------------- helpers ----------------
__device__ __forceinline__ void red_add_v4(float* addr, float4 v) {
    asm volatile("red.global.add.v4.f32 [%0], {%1,%2,%3,%4};"
                 :: "l"(addr), "f"(v.x), "f"(v.y), "f"(v.z), "f"(v.w) : "memory");
}

__device__ __forceinline__ uint32_t f2tf(float x) {
    uint32_t u;
    asm("cvt.rna.tf32.f32 %0, %1;" : "=r"(u) : "f"(x));
    return u;
}

__device__ __forceinline__ void mma8(float* c, const uint32_t* a, const uint32_t* b) {
    asm volatile(
        "mma.sync.aligned.m16n8k8.row.col.f32.tf32.tf32.f32 "
        "{%0,%1,%2,%3},{%4,%5,%6,%7},{%8,%9},{%0,%1,%2,%3};"
        : "+f"(c[0]), "+f"(c[1]), "+f"(c[2]), "+f"(c[3])
        : "r"(a[0]), "r"(a[1]), "r"(a[2]), "r"(a[3]), "r"(b[0]), "r"(b[1]));
}

// ---------------- init ----------------
__global__ void k_init() {
    int i = blockIdx.x * blockDim.x + threadIdx.x;
    int stride = gridDim.x * blockDim.x;
    for (int idx = i; idx < N_ENT*D_EMB; idx += stride) { g_agg[idx] = 0.f; g_out2[idx] = 0.f; }
    for (int idx = i; idx < N_ENT*NH;   idx += stride) g_sum1[idx] = 0.f;
    for (int idx = i; idx < N_ENT;      idx += stride) g_sum2[idx] = 0.f;
    if (i < D_EMB) { g_colsum[i] = 0.f; g_colsq[i] = 0.f; }
}

// ---------------- weight repacks ----------------
__global__ void k_repackB1(const float* __restrict__ W_heads, const float* __restrict__ W_entities) {
    int idx = blockIdx.x * blockDim.x + threadIdx.x;
    if (idx >= 128*768) return;
    int k = idx / 768, c = idx % 768;
    float v;
    if (c < 512) {
        int part = c >> 8;
        int cc = c & 255;
        int h = cc >> 6, d = cc & 63;
        v = W_heads[h*384*64 + (part*128 + k)*64 + d];
    } else {
        v = W_entities[k*256 + (c - 512)];
    }
    g_B1[idx] = v;
}

__global__ void k_repackB1r(const float* __restrict__ W_heads, const float* __restrict__ gat_W) {
    int idx = blockIdx.x * blockDim.x + threadIdx.x;
    if (idx >= 128*512) return;
    int k = idx / 512, c = idx % 512;
    float v;
    if (c < 256) {
        int h = c >> 6, d = c & 63;
        v = W_heads[h*384*64 + (256 + k)*64 + d];
    } else {
        v = gat_W[k*256 + (c - 256)];
    }
    g_B1r[idx] = v;
}

__global__ void k_repackB2(const float* __restrict__ out_W) {
    int idx = blockIdx.x * blockDim.x + threadIdx.x;
    if (idx < 256*512) {
        int k = idx / 512, c = idx % 512;
        g_B2[idx] = (c < 256) ? out_W[k*256 + c] : out_W[(256 + k)*256 + (c - 256)];
    }
    if (idx < 256*256) {
        g_B2r[idx] = out_W[512*256 + idx];
    }
}

// ---------------- 3xTF32 tensor-core GEMM, per-n-tile output pointers ----------------
// C tile for n-block bx is written to Ct[bx] + row*256 + (local col 0..127).
__global__ __launch_bounds__(256, 1) void gemm_tf32(
    const float* __restrict__ A, const float* __restrict__ B,
    float* C0, float* C1, float* C2, float* C3, float* C4, float* C5,
    int M, int K, int lda, int N)
{
    __shared__ float As[128][36];
    __shared__ float Bs[32][136];

    int tid  = threadIdx.x;
    int m0   = blockIdx.y * 128;
    int n0   = blockIdx.x * 128;
    int warp = tid >> 5;
    int lane = tid & 31;
    int g = lane >> 2;
    int t = lane & 3;
    int wm = warp >> 1;
    int wn = warp & 1;

    float* Cb;
    switch (blockIdx.x) {
        case 0: Cb = C0; break;
        case 1: Cb = C1; break;
        case 2: Cb = C2; break;
        case 3: Cb = C3; break;
        case 4: Cb = C4; break;
        default: Cb = C5; break;
    }

    float acc[2][8][4];
    #pragma unroll
    for (int i = 0; i < 2; i++)
        #pragma unroll
        for (int j = 0; j < 8; j++)
            #pragma unroll
            for (int q = 0; q < 4; q++) acc[i][j][q] = 0.f;

    for (int k0 = 0; k0 < K; k0 += 32) {
        #pragma unroll
        for (int i = 0; i < 4; i++) {
            int s = tid + i*256;
            int row = s >> 3;
            int k4  = (s & 7) << 2;
            float4 v = make_float4(0.f, 0.f, 0.f, 0.f);
            if (m0 + row < M)
                v = *(const float4*)(A + (size_t)(m0 + row)*lda + k0 + k4);
            *(float4*)(&As[row][k4]) = v;
        }
        #pragma unroll
        for (int i = 0; i < 4; i++) {
            int s = tid + i*256;
            int k  = s >> 5;
            int n4 = (s & 31) << 2;
            *(float4*)(&Bs[k][n4]) = *(const float4*)(B + (size_t)(k0 + k)*N + n0 + n4);
        }
        __syncthreads();

        #pragma unroll
        for (int ks = 0; ks < 4; ks++) {
            int kk = ks * 8;
            uint32_t ahi[2][4], alo[2][4];
            #pragma unroll
            for (int i = 0; i < 2; i++) {
                int rb = wm*32 + i*16;
                float r0 = As[rb + g][kk + t];
                float r1 = As[rb + g + 8][kk + t];
                float r2 = As[rb + g][kk + t + 4];
                float r3 = As[rb + g + 8][kk + t + 4];
                ahi[i][0] = f2tf(r0); alo[i][0] = f2tf(r0 - __uint_as_float(ahi[i][0]));
                ahi[i][1] = f2tf(r1); alo[i][1] = f2tf(r1 - __uint_as_float(ahi[i][1]));
                ahi[i][2] = f2tf(r2); alo[i][2] = f2tf(r2 - __uint_as_float(ahi[i][2]));
                ahi[i][3] = f2tf(r3); alo[i][3] = f2tf(r3 - __uint_as_float(ahi[i][3]));
            }
            uint32_t bhi[8][2], blo[8][2];
            #pragma unroll
            for (int j = 0; j < 8; j++) {
                int nb = wn*64 + j*8 + g;
                float r0 = Bs[kk + t][nb];
                float r1 = Bs[kk + t + 4][nb];
                bhi[j][0] = f2tf(r0); blo[j][0] = f2tf(r0 - __uint_as_float(bhi[j][0]));
                bhi[j][1] = f2tf(r1); blo[j][1] = f2tf(r1 - __uint_as_float(bhi[j][1]));
            }
            #pragma unroll
            for (int i = 0; i < 2; i++)
                #pragma unroll
                for (int j = 0; j < 8; j++) {
                    mma8(acc[i][j], ahi[i], bhi[j]);
                    mma8(acc[i][j], ahi[i], blo[j]);
                    mma8(acc[i][j], alo[i], bhi[j]);
                }
        }
        __syncthreads();
    }

    #pragma unroll
    for (int i = 0; i < 2; i++) {
        int r0 = m0 + wm*32 + i*16 + g;
        #pragma unroll
        for (int j = 0; j < 8; j++) {
            int col = wn*64 + j*8 + 2*t;
            if (r0 < M)
                *(float2*)(Cb + (size_t)r0*D_EMB + col) = make_float2(acc[i][j][0], acc[i][j][1]);
            if (r0 + 8 < M)
                *(float2*)(Cb + (size_t)(r0 + 8)*D_EMB + col) = make_float2(acc[i][j][2], acc[i][j][3]);
        }
    }
}

// ---------------- attention scalars ----------------
__global__ void k_scal1(const float* __restrict__ a_heads) {
    int idx = blockIdx.x * blockDim.x + threadIdx.x;
    if (idx >= N_ENT*NH) return;
    int v = idx >> 2, h = idx & 3;
    const float* a = a_heads + h*64;
    const float* pr = g_hr + (size_t)v*D_EMB + h*64;
    const float* pc = g_hc + (size_t)v*D_EMB + h*64;
    float s1 = 0.f, s2 = 0.f;
    #pragma unroll 8
    for (int d = 0; d < 64; d++) { float av = a[d]; s1 += pr[d]*av; s2 += pc[d]*av; }
    g_sr[idx] = s1; g_sc[idx] = s2;
}

__global__ void k_srel1(const float* __restrict__ a_heads) {
    int idx = blockIdx.x * blockDim.x + threadIdx.x;
    if (idx >= N_REL*NH) return;
    int v = idx >> 2, h = idx & 3;
    const float* a = a_heads + h*64;
    const float* p = g_relp + v*D_EMB + h*64;
    float s = 0.f;
    #pragma unroll 8
    for (int d = 0; d < 64; d++) s += p[d]*a[d];
    g_srel[idx] = s;
}

// ---------------- layer-1 fused edge pass: edges + logit + exp + sum ----------------
__global__ void k_att1(const int* __restrict__ edge_index, const int* __restrict__ et,
                       const int* __restrict__ ind2) {
    int e = blockIdx.x * blockDim.x + threadIdx.x;
    if (e >= E_TOT) return;
    int r, c;
    float se[NH];
    if (e < E_DIR) {
        r = edge_index[E_DIR + e]; c = edge_index[e];
        int tt = et[e];
        float4 sv = *(const float4*)(g_srel + tt*NH);
        se[0] = sv.x; se[1] = sv.y; se[2] = sv.z; se[3] = sv.w;
    } else {
        int j = e - E_DIR;
        int4 q = *(const int4*)(ind2 + j*4);
        r = q.w; c = q.x;
        float4 s0 = *(const float4*)(g_srel + q.y*NH);
        float4 s1 = *(const float4*)(g_srel + q.z*NH);
        se[0] = s0.x+s1.x; se[1] = s0.y+s1.y; se[2] = s0.z+s1.z; se[3] = s0.w+s1.w;
    }
    g_row[e] = r; g_col[e] = c;
    float4 srv = *(const float4*)(g_sr + r*NH);
    float4 scv = *(const float4*)(g_sc + c*NH);
    float sr[NH] = {srv.x, srv.y, srv.z, srv.w};
    float sc[NH] = {scv.x, scv.y, scv.z, scv.w};
    float w[NH];
    #pragma unroll
    for (int h = 0; h < NH; h++) {
        float z = sr[h] + sc[h] + se[h];
        z = (z > 0.f) ? z : 0.2f*z;
        w[h] = __expf(z);
    }
    *(float4*)(g_lw1 + e*NH) = make_float4(w[0], w[1], w[2], w[3]);
    red_add_v4(g_sum1 + r*NH, make_float4(w[0], w[1], w[2], w[3]));
}

// ---------------- layer-1 aggregation (self-term factored out) ----------------
__global__ void k_agg1(const int* __restrict__ et, const int* __restrict__ ind2) {
    int idx = blockIdx.x * blockDim.x + threadIdx.x;
    if (idx >= E_TOT*64) return;
    int e  = idx >> 6;
    int d4 = (idx & 63) << 2;
    int h  = d4 >> 6;
    int r = g_row[e], c = g_col[e];
    float alpha = g_lw1[e*NH + h] / (g_sum1[r*NH + h] + 1e-16f);
    float4 w = *(const float4*)(g_hc + (size_t)c*D_EMB + d4);
    float4 p;
    if (e < E_DIR) {
        int tt = et[e];
        p = *(const float4*)(g_relp + tt*D_EMB + d4);
    } else {
        int j = e - E_DIR;
        int t0 = ind2[j*4 + 1], t1 = ind2[j*4 + 2];
        float4 p0 = *(const float4*)(g_relp + t0*D_EMB + d4);
        float4 p1 = *(const float4*)(g_relp + t1*D_EMB + d4);
        p = make_float4(p0.x+p1.x, p0.y+p1.y, p0.z+p1.z, p0.w+p1.w);
    }
    float4 s = make_float4(alpha*(w.x+p.x), alpha*(w.y+p.y),
                           alpha*(w.z+p.z), alpha*(w.w+p.w));
    red_add_v4(g_agg + (size_t)r*D_EMB + d4, s);
}

__global__ void k_fin1() {
    int idx = blockIdx.x * blockDim.x + threadIdx.x;
    if (idx >= N_ENT*D_EMB) return;
    int v = idx >> 8;
    int h = (idx & 255) >> 6;
    float z = g_agg[idx];
    if (g_sum1[v*NH + h] > 0.f) z += g_hr[idx];
    g_x[idx] = (z > 0.f) ? z : expm1f(z);
}

// ---------------- layer-2 scalars ----------------
__global__ void k_scal2(const float* __restrict__ out_a) {
    int gt = blockIdx.x * blockDim.x + threadIdx.x;
    int w = gt >> 5, lane = gt & 31;
    if (w >= N_ENT) return;
    float s1 = 0.f, s2 = 0.f;
    for (int d = lane; d < D_EMB; d += 32) {
        float av = out_a[d];
        s1 += g_prow[(size_t)w*D_EMB + d]*av;
        s2 += g_pcol[(size_t)w*D_EMB + d]*av;
    }
    #pragma unroll
    for (int off = 16; off > 0; off >>= 1) {
        s1 += __shfl_xor_sync(0xffffffffu, s1, off);
        s2 += __shfl_xor_sync(0xffffffffu, s2, off);
    }
    if (lane == 0) { g_s2r[w] = s1; g_s2c[w] = s2; }
}

__global__ void k_srel2(const float* __restrict__ out_a) {
    int v = blockIdx.x * blockDim.x + threadIdx.x;
    if (v >= N_REL) return;
    float s = 0.f;
    for (int d = 0; d < D_EMB; d++) s += g_rel2p[v*D_EMB + d]*out_a[d];
    g_srel2[v] = s;
}

// ---------------- layer-2 fused edge pass ----------------
__global__ void k_att2(const int* __restrict__ et, const int* __restrict__ ind2) {
    int e = blockIdx.x * blockDim.x + threadIdx.x;
    if (e >= E_TOT) return;
    int r = g_row[e], c = g_col[e];
    float se;
    if (e < E_DIR) se = g_srel2[et[e]];
    else { int j = e - E_DIR; se = g_srel2[ind2[j*4+1]] + g_srel2[ind2[j*4+2]]; }
    float z = g_s2r[r] + g_s2c[c] + se;
    z = (z > 0.f) ? z : 0.2f*z;
    float w = __expf(z);
    g_lw2[e] = w;
    atomicAdd(&g_sum2[r], w);
}

__global__ void k_agg2(const int* __restrict__ et, const int* __restrict__ ind2) {
    int idx = blockIdx.x * blockDim.x + threadIdx.x;
    if (idx >= E_TOT*64) return;
    int e  = idx >> 6;
    int d4 = (idx & 63) << 2;
    int r = g_row[e], c = g_col[e];
    float alpha = g_lw2[e] / (g_sum2[r] + 1e-16f);
    float4 w = *(const float4*)(g_pcol + (size_t)c*D_EMB + d4);
    float4 p;
    if (e < E_DIR) {
        int tt = et[e];
        p = *(const float4*)(g_rel2p + tt*D_EMB + d4);
    } else {
        int j = e - E_DIR;
        int t0 = ind2[j*4 + 1], t1 = ind2[j*4 + 2];
        float4 p0 = *(const float4*)(g_rel2p + t0*D_EMB + d4);
        float4 p1 = *(const float4*)(g_rel2p + t1*D_EMB + d4);
        p = make_float4(p0.x+p1.x, p0.y+p1.y, p0.z+p1.z, p0.w+p1.w);
    }
    float4 s = make_float4(alpha*(w.x+p.x), alpha*(w.y+p.y),
                           alpha*(w.z+p.z), alpha*(w.w+p.w));
    red_add_v4(g_out2 + (size_t)r*D_EMB + d4, s);
}

// ---------------- finalize + BN ----------------
__global__ void k_fin2() {
    int j = threadIdx.x;
    int v0 = blockIdx.x * 200;
    float s = 0.f, sq = 0.f;
    for (int v = v0; v < v0 + 200 && v < N_ENT; v++) {
        float z = g_out2[(size_t)v*D_EMB + j];
        if (g_sum2[v] > 0.f) z += g_prow[(size_t)v*D_EMB + j];
        z = (z > 0.f) ? z : expm1f(z);
        z += g_ent[(size_t)v*D_EMB + j];
        g_x[(size_t)v*D_EMB + j] = z;
        s += z; sq += z*z;
    }
    atomicAdd(&g_colsum[j], s);
    atomicAdd(&g_colsq[j], sq);
}

__global__ void k_bn_out(const float* __restrict__ gamma, const float* __restrict__ beta,
                         float* __restrict__ out) {
    int i = blockIdx.x * blockDim.x + threadIdx.x;
    if (i < N_ENT*D_EMB) {
        int j = i & 255;
        float mu  = g_colsum[j] * (1.f/N_ENT);
        float var = g_colsq[j] * (1.f/N_ENT) - mu*mu;
        out[i] = (g_x[i] - mu) * rsqrtf(var + 1e-5f) * gamma[j] + beta[j];
    } else if (i < N_ENT*D_EMB + N_REL*D_EMB) {
        out[i] = g_r[i - N_ENT*D_EMB];
    }
}

// ---------------- launch ----------------
extern "C" void kernel_launch(void* const* d_in, const int* in_sizes, int n_in,
                              void* d_out, int out_size) {
    const int*   edge_index = (const int*)d_in[0];
    const int*   edge_type  = (const int*)d_in[1];
    const int*   ind2       = (const int*)d_in[2];
    const float* init_embed = (const float*)d_in[3];
    const float* init_rel   = (const float*)d_in[4];
    const float* W_heads    = (const float*)d_in[5];
    const float* a_heads    = (const float*)d_in[6];
    const float* gat_W      = (const float*)d_in[7];
    const float* out_W      = (const float*)d_in[8];
    const float* out_a      = (const float*)d_in[9];
    const float* W_entities = (const float*)d_in[10];
    const float* bn_gamma   = (const float*)d_in[11];
    const float* bn_beta    = (const float*)d_in[12];
    float* out = (float*)d_out;

    float *p_hr, *p_hc, *p_ent, *p_prow, *p_pcol, *p_relp, *p_r, *p_rel2p, *p_x;
    float *p_B1, *p_B1r, *p_B2, *p_B2r;
    cudaGetSymbolAddress((void**)&p_hr,    g_hr);
    cudaGetSymbolAddress((void**)&p_hc,    g_hc);
    cudaGetSymbolAddress((void**)&p_ent,   g_ent);
    cudaGetSymbolAddress((void**)&p_prow,  g_prow);
    cudaGetSymbolAddress((void**)&p_pcol,  g_pcol);
    cudaGetSymbolAddress((void**)&p_relp,  g_relp);
    cudaGetSymbolAddress((void**)&p_r,     g_r);
    cudaGetSymbolAddress((void**)&p_rel2p, g_rel2p);
    cudaGetSymbolAddress((void**)&p_x,     g_x);
    cudaGetSymbolAddress((void**)&p_B1,    g_B1);
    cudaGetSymbolAddress((void**)&p_B1r,   g_B1r);
    cudaGetSymbolAddress((void**)&p_B2,    g_B2);
    cudaGetSymbolAddress((void**)&p_B2r,   g_B2r);

    const int TB = 256;
    k_init<<<(N_ENT*D_EMB + TB-1)/TB, TB>>>();
    k_repackB1<<<(128*768 + TB-1)/TB, TB>>>(W_heads, W_entities);
    k_repackB1r<<<(128*512 + TB-1)/TB, TB>>>(W_heads, gat_W);
    k_repackB2<<<(256*512 + TB-1)/TB, TB>>>(out_W);

    // layer-1 GEMMs (merged, per-tile outputs)
    gemm_tf32<<<dim3(6, (N_ENT + 127)/128), 256>>>(
        init_embed, p_B1,
        p_hr, p_hr + 128, p_hc, p_hc + 128, p_ent, p_ent + 128,
        N_ENT, 128, 128, 768);
    gemm_tf32<<<dim3(4, (N_REL + 127)/128), 256>>>(
        init_rel, p_B1r,
        p_relp, p_relp + 128, p_r, p_r + 128, p_r, p_r,
        N_REL, 128, 128, 512);

    // layer-1 attention
    k_scal1<<<(N_ENT*NH + TB-1)/TB, TB>>>(a_heads);
    k_srel1<<<(N_REL*NH + TB-1)/TB, TB>>>(a_heads);
    k_att1<<<(E_TOT + TB-1)/TB, TB>>>(edge_index, edge_type, ind2);
    k_agg1<<<(E_TOT*64 + TB-1)/TB, TB>>>(edge_type, ind2);
    k_fin1<<<(N_ENT*D_EMB + TB-1)/TB, TB>>>();

    // layer-2 GEMMs
    gemm_tf32<<<dim3(4, (N_ENT + 127)/128), 256>>>(
        p_x, p_B2,
        p_prow, p_prow + 128, p_pcol, p_pcol + 128, p_pcol, p_pcol,
        N_ENT, 256, 256, 512);
    gemm_tf32<<<dim3(2, (N_REL + 127)/128), 256>>>(
        p_r, p_B2r,
        p_rel2p, p_rel2p + 128, p_rel2p, p_rel2p, p_rel2p, p_rel2p,
        N_REL, 256, 256, 256);

    // layer-2 attention
    k_scal2<<<(N_ENT*32 + TB-1)/TB, TB>>>(out_a);
    k_srel2<<<(N_REL + TB-1)/TB, TB>>>(out_a);
    k_att2<<<(E_TOT + TB-1)/TB, TB>>>(edge_type, ind2);
    k_agg2<<<(E_TOT*64 + TB-1)/TB, TB>>>(edge_type, ind2);

    k_fin2<<<200, 256>>>();
    k_bn_out<<<(N_ENT*D_EMB + N_REL*D_EMB + TB-1)/TB, TB>>>(bn_gamma, bn_beta, out);
}